// round 2
// baseline (speedup 1.0000x reference)
#include <cuda_runtime.h>
#include <math.h>

#define BB 64
#define TT 512
#define DD 512
#define MM (BB*TT)   // 32768

// Scratch for the precomputed projections (192 MB total, static __device__ per harness rules)
__device__ float g_ev[MM*DD];
__device__ float g_leak[MM*DD];
__device__ float g_write[MM*DD];

// ---------------------------------------------------------------------------
// Kernel A: Y[m][n] = act( sum_k X[m][k]*W[k][n] + bias[n] )
// BM=128, BN=128, BK=16, 256 threads, 8x8 per-thread tile.
// ---------------------------------------------------------------------------
template<int ACT>
__global__ __launch_bounds__(256, 2)
void proj_gemm(const float* __restrict__ X, const float* __restrict__ W,
               const float* __restrict__ bias, float* __restrict__ Y)
{
    constexpr int BM = 128, BN = 128, BK = 16;
    __shared__ float As[BM*BK];   // [m][k]  (k contiguous)
    __shared__ float Bs[BK*BN];   // [k][n]  (n contiguous)

    const int tid = threadIdx.x;
    const int m0 = blockIdx.x * BM;
    const int n0 = blockIdx.y * BN;
    const int tx = tid & 15;      // 0..15 -> n sub-tile
    const int ty = tid >> 4;      // 0..15 -> m sub-tile

    // Global-load mapping
    const int arow = tid >> 2;          // 0..63  (rows arow, arow+64)
    const int acol = (tid & 3) * 4;     // 0,4,8,12
    const int brow = tid >> 5;          // 0..7   (rows brow, brow+8)
    const int bcol = (tid & 31) * 4;    // 0..124

    float acc[8][8];
    #pragma unroll
    for (int i = 0; i < 8; i++)
        #pragma unroll
        for (int j = 0; j < 8; j++) acc[i][j] = 0.0f;

    for (int k0 = 0; k0 < DD; k0 += BK) {
        float4 a0 = *(const float4*)&X[(size_t)(m0 + arow     ) * DD + k0 + acol];
        float4 a1 = *(const float4*)&X[(size_t)(m0 + arow + 64) * DD + k0 + acol];
        float4 b0 = *(const float4*)&W[(size_t)(k0 + brow    ) * DD + n0 + bcol];
        float4 b1 = *(const float4*)&W[(size_t)(k0 + brow + 8) * DD + n0 + bcol];
        *(float4*)&As[(arow     ) * BK + acol] = a0;
        *(float4*)&As[(arow + 64) * BK + acol] = a1;
        *(float4*)&Bs[(brow    ) * BN + bcol] = b0;
        *(float4*)&Bs[(brow + 8) * BN + bcol] = b1;
        __syncthreads();

        #pragma unroll
        for (int kk = 0; kk < BK; kk++) {
            float a[8], b[8];
            #pragma unroll
            for (int i = 0; i < 8; i++) a[i] = As[(ty * 8 + i) * BK + kk];
            float4 bA = *(const float4*)&Bs[kk * BN + tx * 8];
            float4 bC = *(const float4*)&Bs[kk * BN + tx * 8 + 4];
            b[0]=bA.x; b[1]=bA.y; b[2]=bA.z; b[3]=bA.w;
            b[4]=bC.x; b[5]=bC.y; b[6]=bC.z; b[7]=bC.w;
            #pragma unroll
            for (int i = 0; i < 8; i++)
                #pragma unroll
                for (int j = 0; j < 8; j++)
                    acc[i][j] = fmaf(a[i], b[j], acc[i][j]);
        }
        __syncthreads();
    }

    #pragma unroll
    for (int i = 0; i < 8; i++) {
        const int m = m0 + ty * 8 + i;
        #pragma unroll
        for (int j = 0; j < 8; j++) {
            const int n = n0 + tx * 8 + j;
            float v = acc[i][j] + bias[n];
            if (ACT == 1) v = 1.0f / (1.0f + expf(-v));
            Y[(size_t)m * DD + n] = v;
        }
    }
}

// ---------------------------------------------------------------------------
// Kernel B: sequential scan. One CTA per batch row (independent recurrences).
// belief lives in SMEM; each thread owns one output column d.
// ---------------------------------------------------------------------------
__global__ __launch_bounds__(512, 1)
void scan_kernel(const float* __restrict__ Wp, const float* __restrict__ bp,
                 float* __restrict__ out)
{
    __shared__ float bel[DD];
    const int b = blockIdx.x;
    const int d = threadIdx.x;

    bel[d] = 0.0f;
    float beld = 0.0f;
    const float bpd = bp[d];

    const float* __restrict__ ev = g_ev    + (size_t)b * TT * DD;
    const float* __restrict__ lk = g_leak  + (size_t)b * TT * DD;
    const float* __restrict__ wr = g_write + (size_t)b * TT * DD;
    float* __restrict__ ob = out + (size_t)b * TT * DD;

    __syncthreads();

    for (int t = 0; t < TT; t++) {
        float acc = bpd;
        // belief_prev @ Wp  : thread d computes one output column.
        // Wp[k*D + d] reads are fully coalesced; bel[k] is a warp broadcast.
        #pragma unroll 8
        for (int k = 0; k < DD; k++)
            acc = fmaf(bel[k], __ldg(&Wp[(size_t)k * DD + d]), acc);

        const int idx = t * DD + d;
        float cand = tanhf(acc + ev[idx]);
        float nb = lk[idx] * beld + wr[idx] * cand;

        __syncthreads();          // all dot-products done before belief update
        bel[d] = nb;
        beld = nb;
        ob[idx] = nb;
        __syncthreads();          // belief visible before next step's reads
    }
}

// ---------------------------------------------------------------------------
// Launch
// ---------------------------------------------------------------------------
extern "C" void kernel_launch(void* const* d_in, const int* in_sizes, int n_in,
                              void* d_out, int out_size)
{
    const float* evseq = (const float*)d_in[0];
    const float* We    = (const float*)d_in[1];
    const float* be    = (const float*)d_in[2];
    const float* Wp    = (const float*)d_in[3];
    const float* bp    = (const float*)d_in[4];
    const float* Wl    = (const float*)d_in[5];
    const float* bl    = (const float*)d_in[6];
    const float* Ww    = (const float*)d_in[7];
    const float* bw    = (const float*)d_in[8];
    float* out = (float*)d_out;

    float *p_ev, *p_leak, *p_write;
    cudaGetSymbolAddress((void**)&p_ev,    g_ev);
    cudaGetSymbolAddress((void**)&p_leak,  g_leak);
    cudaGetSymbolAddress((void**)&p_write, g_write);

    dim3 grid(MM / 128, DD / 128);
    dim3 blk(256);
    proj_gemm<0><<<grid, blk>>>(evseq, We, be, p_ev);
    proj_gemm<1><<<grid, blk>>>(evseq, Wl, bl, p_leak);
    proj_gemm<1><<<grid, blk>>>(evseq, Ww, bw, p_write);

    scan_kernel<<<BB, DD>>>(Wp, bp, out);
}

// round 4
// speedup vs baseline: 2.3847x; 2.3847x over previous
#include <cuda_runtime.h>
#include <math.h>
#include <stdint.h>

#define BB 64
#define TT 512
#define DD 512
#define MM (BB*TT)   // 32768

// Scratch for the precomputed projections (192 MB total)
__device__ float g_ev[MM*DD];
__device__ float g_leak[MM*DD];
__device__ float g_write[MM*DD];

// ---------------------------------------------------------------------------
// Kernel A: Y[m][n] = act( sum_k X[m][k]*W[k][n] + bias[n] )
// BM=128, BN=128, BK=16, 256 threads, 8x8 per-thread tile.
// ---------------------------------------------------------------------------
template<int ACT>
__global__ __launch_bounds__(256, 2)
void proj_gemm(const float* __restrict__ X, const float* __restrict__ W,
               const float* __restrict__ bias, float* __restrict__ Y)
{
    constexpr int BM = 128, BN = 128, BK = 16;
    __shared__ float As[BM*BK];
    __shared__ float Bs[BK*BN];

    const int tid = threadIdx.x;
    const int m0 = blockIdx.x * BM;
    const int n0 = blockIdx.y * BN;
    const int tx = tid & 15;
    const int ty = tid >> 4;

    const int arow = tid >> 2;
    const int acol = (tid & 3) * 4;
    const int brow = tid >> 5;
    const int bcol = (tid & 31) * 4;

    float acc[8][8];
    #pragma unroll
    for (int i = 0; i < 8; i++)
        #pragma unroll
        for (int j = 0; j < 8; j++) acc[i][j] = 0.0f;

    for (int k0 = 0; k0 < DD; k0 += BK) {
        float4 a0 = *(const float4*)&X[(size_t)(m0 + arow     ) * DD + k0 + acol];
        float4 a1 = *(const float4*)&X[(size_t)(m0 + arow + 64) * DD + k0 + acol];
        float4 b0 = *(const float4*)&W[(size_t)(k0 + brow    ) * DD + n0 + bcol];
        float4 b1 = *(const float4*)&W[(size_t)(k0 + brow + 8) * DD + n0 + bcol];
        *(float4*)&As[(arow     ) * BK + acol] = a0;
        *(float4*)&As[(arow + 64) * BK + acol] = a1;
        *(float4*)&Bs[(brow    ) * BN + bcol] = b0;
        *(float4*)&Bs[(brow + 8) * BN + bcol] = b1;
        __syncthreads();

        #pragma unroll
        for (int kk = 0; kk < BK; kk++) {
            float a[8], b[8];
            #pragma unroll
            for (int i = 0; i < 8; i++) a[i] = As[(ty * 8 + i) * BK + kk];
            float4 bA = *(const float4*)&Bs[kk * BN + tx * 8];
            float4 bC = *(const float4*)&Bs[kk * BN + tx * 8 + 4];
            b[0]=bA.x; b[1]=bA.y; b[2]=bA.z; b[3]=bA.w;
            b[4]=bC.x; b[5]=bC.y; b[6]=bC.z; b[7]=bC.w;
            #pragma unroll
            for (int i = 0; i < 8; i++)
                #pragma unroll
                for (int j = 0; j < 8; j++)
                    acc[i][j] = fmaf(a[i], b[j], acc[i][j]);
        }
        __syncthreads();
    }

    #pragma unroll
    for (int i = 0; i < 8; i++) {
        const int m = m0 + ty * 8 + i;
        #pragma unroll
        for (int j = 0; j < 8; j++) {
            const int n = n0 + tx * 8 + j;
            float v = acc[i][j] + bias[n];
            if (ACT == 1) v = 1.0f / (1.0f + expf(-v));
            Y[(size_t)m * DD + n] = v;
        }
    }
}

// ---------------------------------------------------------------------------
// Kernel B: cluster-resident scan.
//   16 clusters x 8 CTAs; each cluster owns 4 batch rows.
//   Each CTA owns 64 output columns; its Wp slice (512x64) lives in REGISTERS
//   (64 floats/thread). Belief: double-buffered SMEM replicated per CTA;
//   owners push their 64-col slice to all 8 CTAs via DSMEM each step.
//   Exactly one barrier.cluster per step (also serves as the CTA barrier
//   protecting sp reuse).
// ---------------------------------------------------------------------------
#define CLUSTER_C 8
#define NCLUST 16
#define BPC 4
#define DLOC 64
#define SCAN_THREADS 512

__global__ __launch_bounds__(SCAN_THREADS, 1) __cluster_dims__(CLUSTER_C, 1, 1)
void scan_cluster_kernel(const float* __restrict__ Wp, const float* __restrict__ bp,
                         float* __restrict__ out)
{
    __shared__ __align__(16) float bel[2][BPC][DD];      // 16 KB double-buffered
    __shared__ __align__(16) float sp[BPC][8][DLOC];     // 8 KB k-section partials

    const int tid     = threadIdx.x;
    const int d_local = tid & 63;
    const int ksec    = tid >> 6;        // 0..7
    const int kbase   = ksec * 64;

    uint32_t rank;
    asm("mov.u32 %0, %%cluster_ctarank;" : "=r"(rank));
    const int cluster_id = blockIdx.x / CLUSTER_C;
    const int b0    = cluster_id * BPC;
    const int dglob = (int)rank * DLOC + d_local;

    // ---- Persistent Wp slice in registers ----
    float w[64];
    #pragma unroll
    for (int j = 0; j < 64; j++)
        w[j] = Wp[(size_t)(kbase + j) * DD + dglob];

    // ---- init belief buffer 0 ----
    for (int i = tid; i < BPC * DD; i += SCAN_THREADS)
        (&bel[0][0][0])[i] = 0.0f;

    // ---- reducer state: threads 0..255, one per (batch, column) ----
    const int  rb     = ksec & 3;
    const bool is_red = (tid < 256);
    float bel_prev = 0.0f;
    float bpv = 0.0f;
    size_t io_base = 0;
    uint32_t ra[2][CLUSTER_C];   // precomputed DSMEM peer addresses per buffer
    if (is_red) {
        bpv = bp[dglob];
        io_base = ((size_t)(b0 + rb) * TT) * DD + dglob;
        #pragma unroll
        for (int buf = 0; buf < 2; buf++) {
            const uint32_t la =
                (uint32_t)__cvta_generic_to_shared(&bel[buf][rb][dglob]);
            #pragma unroll
            for (int p = 0; p < CLUSTER_C; p++) {
                asm("mapa.shared::cluster.u32 %0, %1, %2;"
                    : "=r"(ra[buf][p]) : "r"(la), "r"(p));
            }
        }
    }

    asm volatile("barrier.cluster.arrive.aligned;" ::: "memory");
    asm volatile("barrier.cluster.wait.aligned;"   ::: "memory");

    for (int t = 0; t < TT; t++) {
        const int cur = t & 1;
        const int nxt = cur ^ 1;

        // prefetch gate inputs (latency hidden under matvec)
        float evv = 0.f, lkv = 0.f, wrv = 0.f;
        if (is_red) {
            const size_t idx = io_base + (size_t)t * DD;
            evv = g_ev[idx];
            lkv = g_leak[idx];
            wrv = g_write[idx];
        }

        // ---- matvec partials: this thread's 64-k section x 4 batches ----
        const float4* bl0 = (const float4*)&bel[cur][0][kbase];
        const float4* bl1 = (const float4*)&bel[cur][1][kbase];
        const float4* bl2 = (const float4*)&bel[cur][2][kbase];
        const float4* bl3 = (const float4*)&bel[cur][3][kbase];
        float a0 = 0.f, a1 = 0.f, a2 = 0.f, a3 = 0.f;
        #pragma unroll
        for (int j4 = 0; j4 < 16; j4++) {
            const float4 v0 = bl0[j4];
            const float4 v1 = bl1[j4];
            const float4 v2 = bl2[j4];
            const float4 v3 = bl3[j4];
            a0 = fmaf(v0.x, w[4*j4+0], a0);
            a0 = fmaf(v0.y, w[4*j4+1], a0);
            a0 = fmaf(v0.z, w[4*j4+2], a0);
            a0 = fmaf(v0.w, w[4*j4+3], a0);
            a1 = fmaf(v1.x, w[4*j4+0], a1);
            a1 = fmaf(v1.y, w[4*j4+1], a1);
            a1 = fmaf(v1.z, w[4*j4+2], a1);
            a1 = fmaf(v1.w, w[4*j4+3], a1);
            a2 = fmaf(v2.x, w[4*j4+0], a2);
            a2 = fmaf(v2.y, w[4*j4+1], a2);
            a2 = fmaf(v2.z, w[4*j4+2], a2);
            a2 = fmaf(v2.w, w[4*j4+3], a2);
            a3 = fmaf(v3.x, w[4*j4+0], a3);
            a3 = fmaf(v3.y, w[4*j4+1], a3);
            a3 = fmaf(v3.z, w[4*j4+2], a3);
            a3 = fmaf(v3.w, w[4*j4+3], a3);
        }
        sp[0][ksec][d_local] = a0;
        sp[1][ksec][d_local] = a1;
        sp[2][ksec][d_local] = a2;
        sp[3][ksec][d_local] = a3;
        __syncthreads();

        // ---- reduce + gates + DSMEM broadcast ----
        if (is_red) {
            float s = 0.f;
            #pragma unroll
            for (int q = 0; q < 8; q++) s += sp[rb][q][d_local];
            const float cand = tanhf(s + bpv + evv);
            const float nb   = lkv * bel_prev + wrv * cand;
            bel_prev = nb;

            #pragma unroll
            for (int p = 0; p < CLUSTER_C; p++) {
                asm volatile("st.shared::cluster.f32 [%0], %1;"
                             :: "r"(ra[nxt][p]), "f"(nb) : "memory");
            }
            out[io_base + (size_t)t * DD] = nb;
        }

        // one cluster barrier per step: orders DSMEM writes(t) before
        // reads(t+1) AND protects sp against overwrite at t+1.
        asm volatile("barrier.cluster.arrive.aligned;" ::: "memory");
        asm volatile("barrier.cluster.wait.aligned;"   ::: "memory");
    }
}

// ---------------------------------------------------------------------------
// Launch
// ---------------------------------------------------------------------------
extern "C" void kernel_launch(void* const* d_in, const int* in_sizes, int n_in,
                              void* d_out, int out_size)
{
    const float* evseq = (const float*)d_in[0];
    const float* We    = (const float*)d_in[1];
    const float* be    = (const float*)d_in[2];
    const float* Wp    = (const float*)d_in[3];
    const float* bp    = (const float*)d_in[4];
    const float* Wl    = (const float*)d_in[5];
    const float* bl    = (const float*)d_in[6];
    const float* Ww    = (const float*)d_in[7];
    const float* bw    = (const float*)d_in[8];
    float* out = (float*)d_out;

    float *p_ev, *p_leak, *p_write;
    cudaGetSymbolAddress((void**)&p_ev,    g_ev);
    cudaGetSymbolAddress((void**)&p_leak,  g_leak);
    cudaGetSymbolAddress((void**)&p_write, g_write);

    dim3 grid(MM / 128, DD / 128);
    dim3 blk(256);
    proj_gemm<0><<<grid, blk>>>(evseq, We, be, p_ev);
    proj_gemm<1><<<grid, blk>>>(evseq, Wl, bl, p_leak);
    proj_gemm<1><<<grid, blk>>>(evseq, Ww, bw, p_write);

    scan_cluster_kernel<<<NCLUST * CLUSTER_C, SCAN_THREADS>>>(Wp, bp, out);
}